// round 16
// baseline (speedup 1.0000x reference)
#include <cuda_runtime.h>
#include <cuda_fp16.h>
#include <cstdint>

// CausalAttention B=8, S=2048, D=1024 fp32 via fp16 mma.sync GEMMs.
//   projections: Q/K/V = cast16(x) @ cast16(W)
//   QK: Qh @ Kh^T      (B n-major, ldmatrix)
//   PV: Ph @ Vh        (B k-major [S,D], ldmatrix.trans)
// R16: 512-thread GEMM CTA (16 warps, warp tile 32x32) — R14/15 showed only
//      one 8-warp CTA was resident (2 warps/SMSP, tensor 58%); this doubles
//      warps/SMSP at ~90 regs. Same per-output k-order -> bit-identical error.

constexpr int B_ = 8;
constexpr int S_ = 2048;
constexpr int D_ = 1024;
constexpr int MTOT = B_ * S_;          // 16384

// ---------------- scratch (device globals; allocation-free) ----------------
__device__ __half g_xh[MTOT * D_];
__device__ __half g_Wth[3][D_ * D_];                     // W^T [3][D,D] fp16
__device__ __half g_Qh[MTOT * D_];
__device__ __half g_Kh[MTOT * D_];
__device__ __half g_Vh[MTOT * D_];                       // V [B][S,D] natural
__device__ float  g_Sc[(size_t)B_ * S_ * S_];
__device__ __half g_Ph[(size_t)B_ * S_ * S_];

// ---------------- helpers ----------------
__device__ __forceinline__ uint32_t smem_u32(const void* p) {
    uint32_t a;
    asm("{ .reg .u64 t; cvta.to.shared.u64 t, %1; cvt.u32.u64 %0, t; }"
        : "=r"(a) : "l"(p));
    return a;
}
__device__ __forceinline__ void cp_async16(uint32_t dst, const void* src) {
    asm volatile("cp.async.cg.shared.global [%0], [%1], 16;"
                 :: "r"(dst), "l"(__cvta_generic_to_global(src)) : "memory");
}
__device__ __forceinline__ void cp_commit() {
    asm volatile("cp.async.commit_group;" ::: "memory");
}
template <int N>
__device__ __forceinline__ void cp_wait() {
    asm volatile("cp.async.wait_group %0;" :: "n"(N) : "memory");
}
__device__ __forceinline__ void ldm_x4(uint32_t* r, uint32_t addr) {
    asm("ldmatrix.sync.aligned.m8n8.x4.shared.b16 {%0,%1,%2,%3}, [%4];"
        : "=r"(r[0]), "=r"(r[1]), "=r"(r[2]), "=r"(r[3]) : "r"(addr));
}
__device__ __forceinline__ void ldm_x4t(uint32_t* r, uint32_t addr) {
    asm("ldmatrix.sync.aligned.m8n8.x4.trans.shared.b16 {%0,%1,%2,%3}, [%4];"
        : "=r"(r[0]), "=r"(r[1]), "=r"(r[2]), "=r"(r[3]) : "r"(addr));
}
__device__ __forceinline__ void mma16816(float* c, const uint32_t* a,
                                         uint32_t b0, uint32_t b1) {
    asm("mma.sync.aligned.m16n8k16.row.col.f32.f16.f16.f32 "
        "{%0,%1,%2,%3}, {%4,%5,%6,%7}, {%8,%9}, {%0,%1,%2,%3};"
        : "+f"(c[0]), "+f"(c[1]), "+f"(c[2]), "+f"(c[3])
        : "r"(a[0]), "r"(a[1]), "r"(a[2]), "r"(a[3]), "r"(b0), "r"(b1));
}

// ---------------- cast / transpose / softmax kernels ----------------
__global__ __launch_bounds__(256)
void cast_f32h(const float* __restrict__ in, __half* __restrict__ h, int n4) {
    int i = blockIdx.x * 256 + threadIdx.x;
    if (i >= n4) return;
    float4 v = *reinterpret_cast<const float4*>(in + (size_t)i * 4);
    __half2 hp0 = __floats2half2_rn(v.x, v.y);
    __half2 hp1 = __floats2half2_rn(v.z, v.w);
    uint2 hu;
    hu.x = *reinterpret_cast<uint32_t*>(&hp0);
    hu.y = *reinterpret_cast<uint32_t*>(&hp1);
    *reinterpret_cast<uint2*>(h + (size_t)i * 4) = hu;
}

__global__ __launch_bounds__(256)
void transpose_w3(const float* __restrict__ w0, const float* __restrict__ w1,
                  const float* __restrict__ w2, __half* __restrict__ oh) {
    __shared__ float t[32][33];
    const float* in = (blockIdx.z == 0) ? w0 : (blockIdx.z == 1) ? w1 : w2;
    oh += (size_t)blockIdx.z * D_ * D_;
    int c0 = blockIdx.x * 32, r0 = blockIdx.y * 32;
    int tx = threadIdx.x;
#pragma unroll
    for (int j = 0; j < 4; j++) {
        int ty = threadIdx.y * 4 + j;
        t[ty][tx] = in[(size_t)(r0 + ty) * D_ + c0 + tx];
    }
    __syncthreads();
#pragma unroll
    for (int j = 0; j < 4; j++) {
        int ty = threadIdx.y * 4 + j;
        oh[(size_t)(c0 + ty) * D_ + r0 + tx] = __float2half_rn(t[tx][ty]);
    }
}

__global__ __launch_bounds__(256)
void softmax_h(const float* __restrict__ Sc, __half* __restrict__ Ph) {
    const int r = blockIdx.x, i = r % S_;
    const size_t off = (size_t)r * S_;
    const float* row = Sc + off;
    const int n = i + 1;
    const int nIt = (n + 255) >> 8;
    const int kLim = (n + 127) & ~127;
    const float scale = 0.03125f;                // 1/sqrt(1024)
    const int tid = threadIdx.x;

    float vals[8];
    float m = -INFINITY;
    for (int it = 0; it < nIt; it++) {
        int j = it * 256 + tid;
        float v = (j < n) ? row[j] * scale : -INFINITY;
        vals[it] = v; m = fmaxf(m, v);
    }
    __shared__ float red[8];
#pragma unroll
    for (int o = 16; o > 0; o >>= 1) m = fmaxf(m, __shfl_xor_sync(~0u, m, o));
    if ((tid & 31) == 0) red[tid >> 5] = m;
    __syncthreads();
    float M = red[0];
#pragma unroll
    for (int w = 1; w < 8; w++) M = fmaxf(M, red[w]);
    __syncthreads();
    float ssum = 0.f;
    for (int it = 0; it < nIt; it++) {
        int j = it * 256 + tid;
        float e = (j < n) ? __expf(vals[it] - M) : 0.f;
        vals[it] = e; ssum += e;
    }
#pragma unroll
    for (int o = 16; o > 0; o >>= 1) ssum += __shfl_xor_sync(~0u, ssum, o);
    if ((tid & 31) == 0) red[tid >> 5] = ssum;
    __syncthreads();
    float T = 0.f;
#pragma unroll
    for (int w = 0; w < 8; w++) T += red[w];
    const float inv = 1.f / T;
    for (int it = 0; it < nIt; it++) {
        int j = it * 256 + tid;
        if (j < kLim) {
            float v = (j < n) ? vals[it] * inv : 0.f;
            Ph[off + j] = __float2half_rn(v);
        }
    }
}

// ---------------- fp16 HMMA GEMM (512 threads, warp tile 32x32) ----------------
// BTRANS=0: C = A[M,K] * B[N,K]^T  (B n-major, 128B rows, ldmatrix)
// BTRANS=1: C = A[M,K] * B[K,N]    (B k-major, 256B rows, ldmatrix.trans)
// CTA tile 128x128, BK=64. 16 warps: 4(m) x 4(n). EP: 0 -> fp32 Cf; 2 -> fp16 Ch.
constexpr int TILE_B = 16384;                    // one 16 KB operand tile
constexpr int STG_BYTES = 2 * TILE_B;            // A,B = 32 KB per stage
constexpr int SMEM_BYTES = 2 * STG_BYTES;        // 64 KB
constexpr int GT = 512;                          // GEMM threads

template <int EP, bool CSKIP, bool CLIMK, bool BTRANS>
__global__ __launch_bounds__(GT, 1)
void hmma_gemm(const __half* __restrict__ Ah, const __half* __restrict__ Bh,
               float* __restrict__ Cf, __half* __restrict__ Ch,
               int N, int K, size_t sA, size_t sB, size_t sC)
{
    const int rowBase = blockIdx.y * 128, colBase = blockIdx.x * 128;
    if (CSKIP && colBase > rowBase) return;
    const int kEnd = CLIMK ? (rowBase + 128) : K;
    const int NC = kEnd >> 6;                     // chunks of 64 K

    extern __shared__ char smem[];
    const uint32_t sbase = smem_u32(smem);

    Ah += (size_t)blockIdx.z * sA;
    Bh += (size_t)blockIdx.z * sB;

    const int tid = threadIdx.x, wid = tid >> 5, lid = tid & 31;
    const int wr = wid & 3, wc = wid >> 2;         // warp grid 4(m) x 4(n)

    // A fragments: 2 m16-tiles (rows wr*32 .. wr*32+31)
    uint32_t aRel[2], aXor[2];
#pragma unroll
    for (int mt = 0; mt < 2; mt++) {
        int r = wr * 32 + mt * 16 + (lid & 15);
        aRel[mt] = r * 128;
        aXor[mt] = (r & 7) << 4;
    }
    const uint32_t aHalf = (lid >> 4) * 16;

    // B fragments: 2 n16-tiles (cols wc*32 .. wc*32+31)
    const int g = lid >> 3;
    uint32_t bRel[2], bXor[2];       // BTRANS=0
    uint32_t vRel[2];                // BTRANS=1 (per-ks add = 4096)
    if (!BTRANS) {
#pragma unroll
        for (int nt = 0; nt < 2; nt++) {
            int r = wc * 32 + nt * 16 + ((g & 1) << 3) + (lid & 7);
            bRel[nt] = r * 128;
            bXor[nt] = (r & 7) << 4;
        }
    } else {
        const int kLane = ((lid >> 4) << 3) + (lid & 7);
        const uint32_t lXor = (uint32_t)(lid & 7) << 4;
#pragma unroll
        for (int nt = 0; nt < 2; nt++) {
            uint32_t nByte = (uint32_t)(wc * 32 + nt * 16 + ((g & 1) << 3)) * 2;
            vRel[nt] = kLane * 256 + (nByte ^ lXor);
        }
    }
    const uint32_t bHalf = (g >> 1) * 16;

    float acc[2][4][4];
#pragma unroll
    for (int i = 0; i < 2; i++)
#pragma unroll
        for (int j = 0; j < 4; j++)
#pragma unroll
            for (int k = 0; k < 4; k++) acc[i][j][k] = 0.f;

    auto loadChunk = [&](int c, int buf) {
        const int k0 = c << 6;
        const uint32_t st = sbase + buf * STG_BYTES;
#pragma unroll
        for (int j = 0; j < 2; j++) {
            int idx = j * GT + tid;                    // 0..1023 granules
            {   // A tile: 128 rows x 64 k (128B rows)
                int row = idx >> 3, col = idx & 7;
                uint32_t off = row * 128 + ((col * 16) ^ ((row & 7) << 4));
                cp_async16(st + off, Ah + (size_t)(rowBase + row) * K + k0 + col * 8);
            }
            if (!BTRANS) {
                int row = idx >> 3, col = idx & 7;
                uint32_t off = row * 128 + ((col * 16) ^ ((row & 7) << 4));
                cp_async16(st + TILE_B + off,
                           Bh + (size_t)(colBase + row) * K + k0 + col * 8);
            } else {        // B: 64 k-rows x 128 n (256B rows)
                int row = idx >> 4, col = idx & 15;
                uint32_t off = row * 256 + ((col * 16) ^ ((row & 7) << 4));
                cp_async16(st + TILE_B + off,
                           Bh + (size_t)(k0 + row) * N + colBase + col * 8);
            }
        }
        cp_commit();
    };

    loadChunk(0, 0);

    for (int c = 0; c < NC; c++) {
        const int buf = c & 1;
        cp_wait<0>();
        __syncthreads();
        if (c + 1 < NC) loadChunk(c + 1, buf ^ 1);

        const uint32_t sAh = sbase + buf * STG_BYTES;
        const uint32_t sBh = sAh + TILE_B;
#pragma unroll
        for (int ks = 0; ks < 4; ks++) {
            const uint32_t kb = ks * 32;
            uint32_t ah[2][4], bh[2][4];
#pragma unroll
            for (int nt = 0; nt < 2; nt++) {
                if (!BTRANS)
                    ldm_x4(bh[nt], sBh + bRel[nt] + ((kb + bHalf) ^ bXor[nt]));
                else
                    ldm_x4t(bh[nt], sBh + ks * 4096 + vRel[nt]);
            }
#pragma unroll
            for (int mt = 0; mt < 2; mt++)
                ldm_x4(ah[mt], sAh + aRel[mt] + ((kb + aHalf) ^ aXor[mt]));
#pragma unroll
            for (int mt = 0; mt < 2; mt++)
#pragma unroll
                for (int nt = 0; nt < 2; nt++) {
                    mma16816(acc[mt][2 * nt],     ah[mt], bh[nt][0], bh[nt][2]);
                    mma16816(acc[mt][2 * nt + 1], ah[mt], bh[nt][1], bh[nt][3]);
                }
        }
        __syncthreads();
    }

    // ---- epilogue ----
    const int colW = colBase + wc * 32 + (lid & 3) * 2;
#pragma unroll
    for (int mt = 0; mt < 2; mt++) {
        const int row0 = rowBase + wr * 32 + mt * 16 + (lid >> 2);
#pragma unroll
        for (int nt = 0; nt < 4; nt++) {
            const int col = colW + nt * 8;
            const float* cc = acc[mt][nt];
            if (EP == 0) {
                float* base = Cf + (size_t)blockIdx.z * sC;
                *reinterpret_cast<float2*>(base + (size_t)row0 * N + col) =
                    make_float2(cc[0], cc[1]);
                *reinterpret_cast<float2*>(base + (size_t)(row0 + 8) * N + col) =
                    make_float2(cc[2], cc[3]);
            } else {
#pragma unroll
                for (int h = 0; h < 2; h++) {
                    __half2 hp = __floats2half2_rn(cc[2 * h], cc[2 * h + 1]);
                    size_t o = (size_t)(row0 + h * 8) * N + col;
                    *reinterpret_cast<uint32_t*>(Ch + o) =
                        *reinterpret_cast<uint32_t*>(&hp);
                }
            }
        }
    }
}

// ---------------- launch ----------------
extern "C" void kernel_launch(void* const* d_in, const int* in_sizes, int n_in,
                              void* d_out, int out_size)
{
    const float* x  = (const float*)d_in[0];
    const float* Wq = (const float*)d_in[1];
    const float* Wk = (const float*)d_in[2];
    const float* Wv = (const float*)d_in[3];
    float* out = (float*)d_out;

    __half *xh, *Wth, *Qh, *Kh, *Vh, *Ph;
    float *Sc;
    cudaGetSymbolAddress((void**)&xh, g_xh);
    cudaGetSymbolAddress((void**)&Wth, g_Wth);
    cudaGetSymbolAddress((void**)&Qh, g_Qh);
    cudaGetSymbolAddress((void**)&Kh, g_Kh);
    cudaGetSymbolAddress((void**)&Vh, g_Vh);
    cudaGetSymbolAddress((void**)&Sc, g_Sc);
    cudaGetSymbolAddress((void**)&Ph, g_Ph);

    cudaFuncSetAttribute(hmma_gemm<2, false, false, false>,
                         cudaFuncAttributeMaxDynamicSharedMemorySize, SMEM_BYTES);
    cudaFuncSetAttribute(hmma_gemm<0, true, false, false>,
                         cudaFuncAttributeMaxDynamicSharedMemorySize, SMEM_BYTES);
    cudaFuncSetAttribute(hmma_gemm<0, false, true, true>,
                         cudaFuncAttributeMaxDynamicSharedMemorySize, SMEM_BYTES);

    // 1. cast x to fp16
    cast_f32h<<<(MTOT * D_ / 4 + 255) / 256, 256>>>(x, xh, MTOT * D_ / 4);
    // 2. transpose all 3 weights (one launch) -> fp16 [dout, din]
    transpose_w3<<<dim3(32, 32, 3), dim3(32, 8)>>>(Wq, Wk, Wv, Wth);

    // 3. projections (fp16)
    dim3 gp(D_ / 128, MTOT / 128, 1);
    hmma_gemm<2, false, false, false><<<gp, GT, SMEM_BYTES>>>(
        xh, Wth, nullptr, Qh, D_, D_, 0, 0, 0);
    hmma_gemm<2, false, false, false><<<gp, GT, SMEM_BYTES>>>(
        xh, Wth + (size_t)D_ * D_, nullptr, Kh, D_, D_, 0, 0, 0);
    hmma_gemm<2, false, false, false><<<gp, GT, SMEM_BYTES>>>(
        xh, Wth + 2 * (size_t)D_ * D_, nullptr, Vh, D_, D_, 0, 0, 0);

    // 4. scores = Q K^T (lower-triangular blocks), fp32
    hmma_gemm<0, true, false, false><<<dim3(S_ / 128, S_ / 128, B_), GT, SMEM_BYTES>>>(
        Qh, Kh, Sc, nullptr, S_, D_,
        (size_t)S_ * D_, (size_t)S_ * D_, (size_t)S_ * S_);

    // 5. causal-limited softmax -> fp16 P
    softmax_h<<<B_ * S_, 256>>>(Sc, Ph);

    // 6. out = P V  (V in natural [S,D] layout via ldmatrix.trans)
    hmma_gemm<0, false, true, true><<<dim3(D_ / 128, S_ / 128, B_), GT, SMEM_BYTES>>>(
        Ph, Vh, out, nullptr, D_, S_,
        (size_t)S_ * S_, (size_t)S_ * D_, (size_t)S_ * D_);
}

// round 17
// speedup vs baseline: 1.1283x; 1.1283x over previous
#include <cuda_runtime.h>
#include <cuda_fp16.h>
#include <cstdint>

// CausalAttention B=8, S=2048, D=1024 fp32 via fp16 mma.sync GEMMs.
//   projections: Q/K/V = cast16(x) @ cast16(W)
//   QK: Qh @ Kh^T      (B n-major, ldmatrix)
//   PV: Ph @ Vh        (B k-major [S,D], ldmatrix.trans)
// R17: SMEM-crossbar optimization. R14 vs R16 showed GEMM time tracks
//   crossbar bytes/chunk (ldmatrix redundancy + STS). 4 warps of 64x64
//   (2m x 2n) cut A/B fragment re-reads to 2x/2x: 128 -> 96 KB per chunk.
//   128-thread CTAs -> 2 CTAs/SM at ~190 regs. Same k-order, same error.

constexpr int B_ = 8;
constexpr int S_ = 2048;
constexpr int D_ = 1024;
constexpr int MTOT = B_ * S_;          // 16384

// ---------------- scratch (device globals; allocation-free) ----------------
__device__ __half g_xh[MTOT * D_];
__device__ __half g_Wth[3][D_ * D_];                     // W^T [3][D,D] fp16
__device__ __half g_Qh[MTOT * D_];
__device__ __half g_Kh[MTOT * D_];
__device__ __half g_Vh[MTOT * D_];                       // V [B][S,D] natural
__device__ float  g_Sc[(size_t)B_ * S_ * S_];
__device__ __half g_Ph[(size_t)B_ * S_ * S_];

// ---------------- helpers ----------------
__device__ __forceinline__ uint32_t smem_u32(const void* p) {
    uint32_t a;
    asm("{ .reg .u64 t; cvta.to.shared.u64 t, %1; cvt.u32.u64 %0, t; }"
        : "=r"(a) : "l"(p));
    return a;
}
__device__ __forceinline__ void cp_async16(uint32_t dst, const void* src) {
    asm volatile("cp.async.cg.shared.global [%0], [%1], 16;"
                 :: "r"(dst), "l"(__cvta_generic_to_global(src)) : "memory");
}
__device__ __forceinline__ void cp_commit() {
    asm volatile("cp.async.commit_group;" ::: "memory");
}
template <int N>
__device__ __forceinline__ void cp_wait() {
    asm volatile("cp.async.wait_group %0;" :: "n"(N) : "memory");
}
__device__ __forceinline__ void ldm_x4(uint32_t* r, uint32_t addr) {
    asm("ldmatrix.sync.aligned.m8n8.x4.shared.b16 {%0,%1,%2,%3}, [%4];"
        : "=r"(r[0]), "=r"(r[1]), "=r"(r[2]), "=r"(r[3]) : "r"(addr));
}
__device__ __forceinline__ void ldm_x4t(uint32_t* r, uint32_t addr) {
    asm("ldmatrix.sync.aligned.m8n8.x4.trans.shared.b16 {%0,%1,%2,%3}, [%4];"
        : "=r"(r[0]), "=r"(r[1]), "=r"(r[2]), "=r"(r[3]) : "r"(addr));
}
__device__ __forceinline__ void mma16816(float* c, const uint32_t* a,
                                         uint32_t b0, uint32_t b1) {
    asm("mma.sync.aligned.m16n8k16.row.col.f32.f16.f16.f32 "
        "{%0,%1,%2,%3}, {%4,%5,%6,%7}, {%8,%9}, {%0,%1,%2,%3};"
        : "+f"(c[0]), "+f"(c[1]), "+f"(c[2]), "+f"(c[3])
        : "r"(a[0]), "r"(a[1]), "r"(a[2]), "r"(a[3]), "r"(b0), "r"(b1));
}

// ---------------- cast / transpose / softmax kernels ----------------
__global__ __launch_bounds__(256)
void cast_f32h(const float* __restrict__ in, __half* __restrict__ h, int n4) {
    int i = blockIdx.x * 256 + threadIdx.x;
    if (i >= n4) return;
    float4 v = *reinterpret_cast<const float4*>(in + (size_t)i * 4);
    __half2 hp0 = __floats2half2_rn(v.x, v.y);
    __half2 hp1 = __floats2half2_rn(v.z, v.w);
    uint2 hu;
    hu.x = *reinterpret_cast<uint32_t*>(&hp0);
    hu.y = *reinterpret_cast<uint32_t*>(&hp1);
    *reinterpret_cast<uint2*>(h + (size_t)i * 4) = hu;
}

__global__ __launch_bounds__(256)
void transpose_w3(const float* __restrict__ w0, const float* __restrict__ w1,
                  const float* __restrict__ w2, __half* __restrict__ oh) {
    __shared__ float t[32][33];
    const float* in = (blockIdx.z == 0) ? w0 : (blockIdx.z == 1) ? w1 : w2;
    oh += (size_t)blockIdx.z * D_ * D_;
    int c0 = blockIdx.x * 32, r0 = blockIdx.y * 32;
    int tx = threadIdx.x;
#pragma unroll
    for (int j = 0; j < 4; j++) {
        int ty = threadIdx.y * 4 + j;
        t[ty][tx] = in[(size_t)(r0 + ty) * D_ + c0 + tx];
    }
    __syncthreads();
#pragma unroll
    for (int j = 0; j < 4; j++) {
        int ty = threadIdx.y * 4 + j;
        oh[(size_t)(c0 + ty) * D_ + r0 + tx] = __float2half_rn(t[tx][ty]);
    }
}

__global__ __launch_bounds__(256)
void softmax_h(const float* __restrict__ Sc, __half* __restrict__ Ph) {
    const int r = blockIdx.x, i = r % S_;
    const size_t off = (size_t)r * S_;
    const float* row = Sc + off;
    const int n = i + 1;
    const int nIt = (n + 255) >> 8;
    const int kLim = (n + 127) & ~127;
    const float scale = 0.03125f;                // 1/sqrt(1024)
    const int tid = threadIdx.x;

    float vals[8];
    float m = -INFINITY;
    for (int it = 0; it < nIt; it++) {
        int j = it * 256 + tid;
        float v = (j < n) ? row[j] * scale : -INFINITY;
        vals[it] = v; m = fmaxf(m, v);
    }
    __shared__ float red[8];
#pragma unroll
    for (int o = 16; o > 0; o >>= 1) m = fmaxf(m, __shfl_xor_sync(~0u, m, o));
    if ((tid & 31) == 0) red[tid >> 5] = m;
    __syncthreads();
    float M = red[0];
#pragma unroll
    for (int w = 1; w < 8; w++) M = fmaxf(M, red[w]);
    __syncthreads();
    float ssum = 0.f;
    for (int it = 0; it < nIt; it++) {
        int j = it * 256 + tid;
        float e = (j < n) ? __expf(vals[it] - M) : 0.f;
        vals[it] = e; ssum += e;
    }
#pragma unroll
    for (int o = 16; o > 0; o >>= 1) ssum += __shfl_xor_sync(~0u, ssum, o);
    if ((tid & 31) == 0) red[tid >> 5] = ssum;
    __syncthreads();
    float T = 0.f;
#pragma unroll
    for (int w = 0; w < 8; w++) T += red[w];
    const float inv = 1.f / T;
    for (int it = 0; it < nIt; it++) {
        int j = it * 256 + tid;
        if (j < kLim) {
            float v = (j < n) ? vals[it] * inv : 0.f;
            Ph[off + j] = __float2half_rn(v);
        }
    }
}

// ---------------- fp16 HMMA GEMM (128 threads, warp tile 64x64) ----------------
// BTRANS=0: C = A[M,K] * B[N,K]^T  (B n-major, 128B rows, ldmatrix)
// BTRANS=1: C = A[M,K] * B[K,N]    (B k-major, 256B rows, ldmatrix.trans)
// CTA tile 128x128, BK=64. 4 warps: 2(m) x 2(n). EP: 0 -> fp32 Cf; 2 -> fp16 Ch.
constexpr int TILE_B = 16384;                    // one 16 KB operand tile
constexpr int STG_BYTES = 2 * TILE_B;            // A,B = 32 KB per stage
constexpr int SMEM_BYTES = 2 * STG_BYTES;        // 64 KB
constexpr int GT = 128;                          // GEMM threads

template <int EP, bool CSKIP, bool CLIMK, bool BTRANS>
__global__ __launch_bounds__(GT, 2)
void hmma_gemm(const __half* __restrict__ Ah, const __half* __restrict__ Bh,
               float* __restrict__ Cf, __half* __restrict__ Ch,
               int N, int K, size_t sA, size_t sB, size_t sC)
{
    const int rowBase = blockIdx.y * 128, colBase = blockIdx.x * 128;
    if (CSKIP && colBase > rowBase) return;
    const int kEnd = CLIMK ? (rowBase + 128) : K;
    const int NC = kEnd >> 6;                     // chunks of 64 K

    extern __shared__ char smem[];
    const uint32_t sbase = smem_u32(smem);

    Ah += (size_t)blockIdx.z * sA;
    Bh += (size_t)blockIdx.z * sB;

    const int tid = threadIdx.x, wid = tid >> 5, lid = tid & 31;
    const int wr = wid & 1, wc = wid >> 1;         // warp grid 2(m) x 2(n)

    // A fragments: 4 m16-tiles (rows wr*64 .. wr*64+63)
    uint32_t aRel[4], aXor[4];
#pragma unroll
    for (int mt = 0; mt < 4; mt++) {
        int r = wr * 64 + mt * 16 + (lid & 15);
        aRel[mt] = r * 128;
        aXor[mt] = (r & 7) << 4;
    }
    const uint32_t aHalf = (lid >> 4) * 16;

    // B fragments: 4 n16-tiles (cols wc*64 .. wc*64+63)
    const int g = lid >> 3;
    uint32_t bRel[4], bXor[4];       // BTRANS=0
    uint32_t vRel[4];                // BTRANS=1 (per-ks add = 4096)
    if (!BTRANS) {
#pragma unroll
        for (int nt = 0; nt < 4; nt++) {
            int r = wc * 64 + nt * 16 + ((g & 1) << 3) + (lid & 7);
            bRel[nt] = r * 128;
            bXor[nt] = (r & 7) << 4;
        }
    } else {
        const int kLane = ((lid >> 4) << 3) + (lid & 7);
        const uint32_t lXor = (uint32_t)(lid & 7) << 4;
#pragma unroll
        for (int nt = 0; nt < 4; nt++) {
            uint32_t nByte = (uint32_t)(wc * 64 + nt * 16 + ((g & 1) << 3)) * 2;
            vRel[nt] = kLane * 256 + (nByte ^ lXor);
        }
    }
    const uint32_t bHalf = (g >> 1) * 16;

    float acc[4][8][4];
#pragma unroll
    for (int i = 0; i < 4; i++)
#pragma unroll
        for (int j = 0; j < 8; j++)
#pragma unroll
            for (int k = 0; k < 4; k++) acc[i][j][k] = 0.f;

    auto loadChunk = [&](int c, int buf) {
        const int k0 = c << 6;
        const uint32_t st = sbase + buf * STG_BYTES;
#pragma unroll
        for (int j = 0; j < 8; j++) {
            int idx = j * GT + tid;                    // 0..1023 granules
            {   // A tile: 128 rows x 64 k (128B rows)
                int row = idx >> 3, col = idx & 7;
                uint32_t off = row * 128 + ((col * 16) ^ ((row & 7) << 4));
                cp_async16(st + off, Ah + (size_t)(rowBase + row) * K + k0 + col * 8);
            }
            if (!BTRANS) {
                int row = idx >> 3, col = idx & 7;
                uint32_t off = row * 128 + ((col * 16) ^ ((row & 7) << 4));
                cp_async16(st + TILE_B + off,
                           Bh + (size_t)(colBase + row) * K + k0 + col * 8);
            } else {        // B: 64 k-rows x 128 n (256B rows)
                int row = idx >> 4, col = idx & 15;
                uint32_t off = row * 256 + ((col * 16) ^ ((row & 7) << 4));
                cp_async16(st + TILE_B + off,
                           Bh + (size_t)(k0 + row) * N + colBase + col * 8);
            }
        }
        cp_commit();
    };

    loadChunk(0, 0);

    for (int c = 0; c < NC; c++) {
        const int buf = c & 1;
        cp_wait<0>();
        __syncthreads();
        if (c + 1 < NC) loadChunk(c + 1, buf ^ 1);

        const uint32_t sAh = sbase + buf * STG_BYTES;
        const uint32_t sBh = sAh + TILE_B;
#pragma unroll
        for (int ks = 0; ks < 4; ks++) {
            const uint32_t kb = ks * 32;
            uint32_t ah[4][4], bh[4][4];
#pragma unroll
            for (int nt = 0; nt < 4; nt++) {
                if (!BTRANS)
                    ldm_x4(bh[nt], sBh + bRel[nt] + ((kb + bHalf) ^ bXor[nt]));
                else
                    ldm_x4t(bh[nt], sBh + ks * 4096 + vRel[nt]);
            }
#pragma unroll
            for (int mt = 0; mt < 4; mt++)
                ldm_x4(ah[mt], sAh + aRel[mt] + ((kb + aHalf) ^ aXor[mt]));
#pragma unroll
            for (int mt = 0; mt < 4; mt++)
#pragma unroll
                for (int nt = 0; nt < 4; nt++) {
                    mma16816(acc[mt][2 * nt],     ah[mt], bh[nt][0], bh[nt][2]);
                    mma16816(acc[mt][2 * nt + 1], ah[mt], bh[nt][1], bh[nt][3]);
                }
        }
        __syncthreads();
    }

    // ---- epilogue ----
    const int colW = colBase + wc * 64 + (lid & 3) * 2;
#pragma unroll
    for (int mt = 0; mt < 4; mt++) {
        const int row0 = rowBase + wr * 64 + mt * 16 + (lid >> 2);
#pragma unroll
        for (int nt = 0; nt < 8; nt++) {
            const int col = colW + nt * 8;
            const float* cc = acc[mt][nt];
            if (EP == 0) {
                float* base = Cf + (size_t)blockIdx.z * sC;
                *reinterpret_cast<float2*>(base + (size_t)row0 * N + col) =
                    make_float2(cc[0], cc[1]);
                *reinterpret_cast<float2*>(base + (size_t)(row0 + 8) * N + col) =
                    make_float2(cc[2], cc[3]);
            } else {
#pragma unroll
                for (int h = 0; h < 2; h++) {
                    __half2 hp = __floats2half2_rn(cc[2 * h], cc[2 * h + 1]);
                    size_t o = (size_t)(row0 + h * 8) * N + col;
                    *reinterpret_cast<uint32_t*>(Ch + o) =
                        *reinterpret_cast<uint32_t*>(&hp);
                }
            }
        }
    }
}

// ---------------- launch ----------------
extern "C" void kernel_launch(void* const* d_in, const int* in_sizes, int n_in,
                              void* d_out, int out_size)
{
    const float* x  = (const float*)d_in[0];
    const float* Wq = (const float*)d_in[1];
    const float* Wk = (const float*)d_in[2];
    const float* Wv = (const float*)d_in[3];
    float* out = (float*)d_out;

    __half *xh, *Wth, *Qh, *Kh, *Vh, *Ph;
    float *Sc;
    cudaGetSymbolAddress((void**)&xh, g_xh);
    cudaGetSymbolAddress((void**)&Wth, g_Wth);
    cudaGetSymbolAddress((void**)&Qh, g_Qh);
    cudaGetSymbolAddress((void**)&Kh, g_Kh);
    cudaGetSymbolAddress((void**)&Vh, g_Vh);
    cudaGetSymbolAddress((void**)&Sc, g_Sc);
    cudaGetSymbolAddress((void**)&Ph, g_Ph);

    cudaFuncSetAttribute(hmma_gemm<2, false, false, false>,
                         cudaFuncAttributeMaxDynamicSharedMemorySize, SMEM_BYTES);
    cudaFuncSetAttribute(hmma_gemm<0, true, false, false>,
                         cudaFuncAttributeMaxDynamicSharedMemorySize, SMEM_BYTES);
    cudaFuncSetAttribute(hmma_gemm<0, false, true, true>,
                         cudaFuncAttributeMaxDynamicSharedMemorySize, SMEM_BYTES);

    // 1. cast x to fp16
    cast_f32h<<<(MTOT * D_ / 4 + 255) / 256, 256>>>(x, xh, MTOT * D_ / 4);
    // 2. transpose all 3 weights (one launch) -> fp16 [dout, din]
    transpose_w3<<<dim3(32, 32, 3), dim3(32, 8)>>>(Wq, Wk, Wv, Wth);

    // 3. projections (fp16)
    dim3 gp(D_ / 128, MTOT / 128, 1);
    hmma_gemm<2, false, false, false><<<gp, GT, SMEM_BYTES>>>(
        xh, Wth, nullptr, Qh, D_, D_, 0, 0, 0);
    hmma_gemm<2, false, false, false><<<gp, GT, SMEM_BYTES>>>(
        xh, Wth + (size_t)D_ * D_, nullptr, Kh, D_, D_, 0, 0, 0);
    hmma_gemm<2, false, false, false><<<gp, GT, SMEM_BYTES>>>(
        xh, Wth + 2 * (size_t)D_ * D_, nullptr, Vh, D_, D_, 0, 0, 0);

    // 4. scores = Q K^T (lower-triangular blocks), fp32
    hmma_gemm<0, true, false, false><<<dim3(S_ / 128, S_ / 128, B_), GT, SMEM_BYTES>>>(
        Qh, Kh, Sc, nullptr, S_, D_,
        (size_t)S_ * D_, (size_t)S_ * D_, (size_t)S_ * S_);

    // 5. causal-limited softmax -> fp16 P
    softmax_h<<<B_ * S_, 256>>>(Sc, Ph);

    // 6. out = P V  (V in natural [S,D] layout via ldmatrix.trans)
    hmma_gemm<0, false, true, true><<<dim3(D_ / 128, S_ / 128, B_), GT, SMEM_BYTES>>>(
        Ph, Vh, out, nullptr, D_, S_,
        (size_t)S_ * S_, (size_t)S_ * D_, (size_t)S_ * D_);
}